// round 1
// baseline (speedup 1.0000x reference)
#include <cuda_runtime.h>
#include <math.h>

// Problem constants: B=4, A=32, I=512, D=256  -> 65536 rows of dim 256, fp32.
#define DIM 256
#define TM 64           // rows per CTA
#define KT 16           // k-tile rows staged in smem
#define THREADS 256

struct Smem {
    float x0[TM * DIM];     // 64 KB
    float x1[TM * DIM];     // 64 KB
    float w[KT * DIM];      // 16 KB weight k-tile
    float sc0[TM];
    float sc1[TM];
};
#define SMEM_BYTES ((int)sizeof(Smem))

// One pass of acc += XsA(64x256) @ Wg(256x256), W streamed via smem k-tiles.
// Thread (tx,ty) owns rows ty*8..ty*8+7 and cols tx + c*32 (c=0..7).
__device__ __forceinline__ void gemm_pass(const float* __restrict__ XsA,
                                          const float* __restrict__ Wg,
                                          float* __restrict__ Ws,
                                          float acc[8][8], int tx, int ty) {
    const int tid = ty * 32 + tx;
    for (int kt = 0; kt < DIM / KT; ++kt) {
        __syncthreads();   // Ws reuse + (first iter) X-tile writes visible
        // stage KTxDIM weight tile: 4096 floats = 1024 float4, 4 per thread
        const float4* wg4 = reinterpret_cast<const float4*>(Wg + kt * KT * DIM);
        float4* ws4 = reinterpret_cast<float4*>(Ws);
#pragma unroll
        for (int j = 0; j < (KT * DIM / 4) / THREADS; ++j)
            ws4[tid + j * THREADS] = wg4[tid + j * THREADS];
        __syncthreads();
#pragma unroll
        for (int k = 0; k < KT; ++k) {
            float a[8], b[8];
#pragma unroll
            for (int i = 0; i < 8; ++i)
                a[i] = XsA[(ty * 8 + i) * DIM + kt * KT + k];   // warp broadcast
#pragma unroll
            for (int c = 0; c < 8; ++c)
                b[c] = Ws[k * DIM + tx + c * 32];               // conflict-free
#pragma unroll
            for (int i = 0; i < 8; ++i)
#pragma unroll
                for (int c = 0; c < 8; ++c)
                    acc[i][c] = fmaf(a[i], b[c], acc[i][c]);
        }
    }
}

__global__ void __launch_bounds__(THREADS, 1)
fused_cross_attn_kernel(const float* __restrict__ i0,
                        const float* __restrict__ i1,
                        const float* __restrict__ W1,
                        const float* __restrict__ W2,
                        const float* __restrict__ A1,
                        const float* __restrict__ A2,
                        float* __restrict__ out) {
    extern __shared__ float smem_raw[];
    Smem* s = reinterpret_cast<Smem*>(smem_raw);
    const int tid = threadIdx.x;
    const int tx = tid & 31;
    const int ty = tid >> 5;
    const size_t rowbase = (size_t)blockIdx.x * TM;

    // ---- load X0/X1 tiles (coalesced float4) ----
    const float4* g0 = reinterpret_cast<const float4*>(i0 + rowbase * DIM);
    const float4* g1 = reinterpret_cast<const float4*>(i1 + rowbase * DIM);
    float4* s0v = reinterpret_cast<float4*>(s->x0);
    float4* s1v = reinterpret_cast<float4*>(s->x1);
#pragma unroll
    for (int j = 0; j < (TM * DIM / 4) / THREADS; ++j) {   // 16 iters
        s0v[tid + j * THREADS] = g0[tid + j * THREADS];
        s1v[tid + j * THREADS] = g1[tid + j * THREADS];
    }
    // (gemm_pass begins with __syncthreads, covering these writes)

    // ---- Pass 1: U0 = X1 @ attn1 ; s0 = rowdot(U0, X0) ----
    {
        float acc[8][8];
#pragma unroll
        for (int i = 0; i < 8; ++i)
#pragma unroll
            for (int c = 0; c < 8; ++c) acc[i][c] = 0.f;
        gemm_pass(s->x1, A1, s->w, acc, tx, ty);
#pragma unroll
        for (int i = 0; i < 8; ++i) {
            float p = 0.f;
            const int row = ty * 8 + i;
#pragma unroll
            for (int c = 0; c < 8; ++c)
                p += acc[i][c] * s->x0[row * DIM + tx + c * 32];
#pragma unroll
            for (int off = 16; off; off >>= 1)
                p += __shfl_xor_sync(0xFFFFFFFFu, p, off);
            if (tx == 0)
                s->sc0[row] = 1.f + 1.f / (1.f + expf(-p));
        }
    }

    // ---- Pass 2: U1 = X0 @ attn2 ; s1 = rowdot(U1, X1) ----
    {
        float acc[8][8];
#pragma unroll
        for (int i = 0; i < 8; ++i)
#pragma unroll
            for (int c = 0; c < 8; ++c) acc[i][c] = 0.f;
        gemm_pass(s->x0, A2, s->w, acc, tx, ty);
#pragma unroll
        for (int i = 0; i < 8; ++i) {
            float p = 0.f;
            const int row = ty * 8 + i;
#pragma unroll
            for (int c = 0; c < 8; ++c)
                p += acc[i][c] * s->x1[row * DIM + tx + c * 32];
#pragma unroll
            for (int off = 16; off; off >>= 1)
                p += __shfl_xor_sync(0xFFFFFFFFu, p, off);
            if (tx == 0)
                s->sc1[row] = 1.f + 1.f / (1.f + expf(-p));
        }
    }
    __syncthreads();   // sc0/sc1 visible; all gate reads of x0/x1 finished

    // ---- scale tiles in place: r = x * (1 + g) ----
#pragma unroll
    for (int j = 0; j < (TM * DIM / 4) / THREADS; ++j) {
        const int f4 = tid + j * THREADS;
        const int row = f4 >> 6;           // 64 float4 per row
        float sc = s->sc0[row];
        float4 v = s0v[f4];
        v.x *= sc; v.y *= sc; v.z *= sc; v.w *= sc;
        s0v[f4] = v;
        sc = s->sc1[row];
        v = s1v[f4];
        v.x *= sc; v.y *= sc; v.z *= sc; v.w *= sc;
        s1v[f4] = v;
    }
    // (gemm_pass's leading __syncthreads covers the scaling writes)

    // ---- Pass 3+4: OUT = R0 @ W1 + R1 @ W2 ----
    {
        float acc[8][8];
#pragma unroll
        for (int i = 0; i < 8; ++i)
#pragma unroll
            for (int c = 0; c < 8; ++c) acc[i][c] = 0.f;
        gemm_pass(s->x0, W1, s->w, acc, tx, ty);
        gemm_pass(s->x1, W2, s->w, acc, tx, ty);

        // coalesced store
#pragma unroll
        for (int i = 0; i < 8; ++i) {
            const size_t row = rowbase + ty * 8 + i;
#pragma unroll
            for (int c = 0; c < 8; ++c)
                out[row * DIM + tx + c * 32] = acc[i][c];
        }
    }
}

extern "C" void kernel_launch(void* const* d_in, const int* in_sizes, int n_in,
                              void* d_out, int out_size) {
    const float* i0 = (const float*)d_in[0];
    const float* i1 = (const float*)d_in[1];
    const float* W1 = (const float*)d_in[2];
    const float* W2 = (const float*)d_in[3];
    const float* A1 = (const float*)d_in[4];
    const float* A2 = (const float*)d_in[5];
    float* out = (float*)d_out;

    const int rows = in_sizes[0] / DIM;      // 65536
    const int grid = rows / TM;              // 1024

    cudaFuncSetAttribute(fused_cross_attn_kernel,
                         cudaFuncAttributeMaxDynamicSharedMemorySize, SMEM_BYTES);
    fused_cross_attn_kernel<<<grid, THREADS, SMEM_BYTES>>>(i0, i1, W1, W2, A1, A2, out);
    (void)n_in; (void)out_size;
}

// round 3
// speedup vs baseline: 3.0545x; 3.0545x over previous
#include <cuda_runtime.h>
#include <cstdint>
#include <math.h>

#define DIM 256
#define TM 128
#define THREADS 256

#define PAD_X 68                 // 68 % 32 == 4 -> conflict-free A frag loads
#define PAD_W 264                // 264 % 32 == 8 -> conflict-free B frag loads
#define XS_FLOATS (128 * PAD_X)  // 8704 floats = 34816 B
#define WS_FLOATS (64 * PAD_W)   // 16896 floats = 67584 B
#define BUF_FLOATS (XS_FLOATS + WS_FLOATS)
#define SMEM_BYTES (2 * BUF_FLOATS * 4)   // 204800 B

__device__ __forceinline__ uint32_t smem_u32(const void* p) {
    uint32_t a;
    asm("{ .reg .u64 t; cvta.to.shared.u64 t, %1; cvt.u32.u64 %0, t; }" : "=r"(a) : "l"(p));
    return a;
}
__device__ __forceinline__ void cp16(uint32_t s, const float* g) {
    asm volatile("cp.async.cg.shared.global [%0], [%1], 16;" :: "r"(s), "l"(g));
}
#define CP_COMMIT() asm volatile("cp.async.commit_group;" ::: "memory")
#define CP_WAIT1()  asm volatile("cp.async.wait_group 1;" ::: "memory")
#define CP_WAIT0()  asm volatile("cp.async.wait_group 0;" ::: "memory")

__device__ __forceinline__ uint32_t to_tf32(float x) {
    uint32_t r;
    asm("cvt.rna.tf32.f32 %0, %1;" : "=r"(r) : "f"(x));
    return r;
}
__device__ __forceinline__ void mma8(float* c, const uint32_t* a, const uint32_t* b) {
    asm volatile(
        "mma.sync.aligned.m16n8k8.row.col.f32.tf32.tf32.f32 "
        "{%0,%1,%2,%3}, {%4,%5,%6,%7}, {%8,%9}, {%0,%1,%2,%3};"
        : "+f"(c[0]), "+f"(c[1]), "+f"(c[2]), "+f"(c[3])
        : "r"(a[0]), "r"(a[1]), "r"(a[2]), "r"(a[3]), "r"(b[0]), "r"(b[1]));
}

// ---------- one KC=64 chunk of [128 x 256] += X(128xKC) @ W(KCx256) ----------
template <bool SCALE>
__device__ __forceinline__ void gemm_chunk(const float* __restrict__ xs,
                                           const float* __restrict__ ws,
                                           float (&acc)[2][16][4],
                                           const float (&sc)[2][2],
                                           int wm, int wn, int lq, int lr) {
#pragma unroll
    for (int ks = 0; ks < 8; ++ks) {
        uint32_t ua[2][4];
#pragma unroll
        for (int mt = 0; mt < 2; ++mt) {
            const int r = wm * 32 + mt * 16 + lq;
            const int c = ks * 8 + lr;
            float a0 = xs[r * PAD_X + c];
            float a1 = xs[(r + 8) * PAD_X + c];
            float a2 = xs[r * PAD_X + c + 4];
            float a3 = xs[(r + 8) * PAD_X + c + 4];
            if (SCALE) {
                a0 *= sc[mt][0]; a1 *= sc[mt][1];
                a2 *= sc[mt][0]; a3 *= sc[mt][1];
            }
            ua[mt][0] = to_tf32(a0); ua[mt][1] = to_tf32(a1);
            ua[mt][2] = to_tf32(a2); ua[mt][3] = to_tf32(a3);
        }
#pragma unroll
        for (int nt = 0; nt < 16; ++nt) {
            const int kr = ks * 8 + lr;
            const int n = wn * 128 + nt * 8 + lq;
            uint32_t b[2];
            b[0] = to_tf32(ws[kr * PAD_W + n]);
            b[1] = to_tf32(ws[(kr + 4) * PAD_W + n]);
            mma8(acc[0][nt], ua[0], b);
            mma8(acc[1][nt], ua[1], b);
        }
    }
}

__device__ __forceinline__ void zero_acc(float (&acc)[2][16][4]) {
#pragma unroll
    for (int mt = 0; mt < 2; ++mt)
#pragma unroll
        for (int nt = 0; nt < 16; ++nt)
#pragma unroll
            for (int q = 0; q < 4; ++q) acc[mt][nt][q] = 0.f;
}

// rowdot(acc_fragment, Xo) -> per-row partial sums in s_g[g][wn][row]
__device__ __forceinline__ void gate_dot(const float* __restrict__ Xo,
                                         const float (&acc)[2][16][4], int g,
                                         int wm, int wn, int lq, int lr,
                                         float (*s_g)[2][128]) {
    float pr[2][2] = {{0.f, 0.f}, {0.f, 0.f}};
#pragma unroll
    for (int mt = 0; mt < 2; ++mt) {
        const int r0 = wm * 32 + mt * 16 + lq;
#pragma unroll
        for (int nt = 0; nt < 16; ++nt) {
            const int cb = wn * 128 + nt * 8 + lr * 2;
            float2 v0 = *reinterpret_cast<const float2*>(Xo + (size_t)r0 * DIM + cb);
            float2 v1 = *reinterpret_cast<const float2*>(Xo + (size_t)(r0 + 8) * DIM + cb);
            pr[mt][0] += acc[mt][nt][0] * v0.x + acc[mt][nt][1] * v0.y;
            pr[mt][1] += acc[mt][nt][2] * v1.x + acc[mt][nt][3] * v1.y;
        }
    }
#pragma unroll
    for (int off = 1; off <= 2; off <<= 1)
#pragma unroll
        for (int mt = 0; mt < 2; ++mt) {
            pr[mt][0] += __shfl_xor_sync(0xFFFFFFFFu, pr[mt][0], off);
            pr[mt][1] += __shfl_xor_sync(0xFFFFFFFFu, pr[mt][1], off);
        }
    if (lr == 0) {
#pragma unroll
        for (int mt = 0; mt < 2; ++mt) {
            s_g[g][wn][wm * 32 + mt * 16 + lq] = pr[mt][0];
            s_g[g][wn][wm * 32 + mt * 16 + lq + 8] = pr[mt][1];
        }
    }
}

__global__ void __launch_bounds__(THREADS, 1)
fused_mma_kernel(const float* __restrict__ i0, const float* __restrict__ i1,
                 const float* __restrict__ W1, const float* __restrict__ W2,
                 const float* __restrict__ A1, const float* __restrict__ A2,
                 float* __restrict__ out) {
    extern __shared__ float dyn[];
    __shared__ float s_g[2][2][128];
    __shared__ float s_sc[2][128];

    const int tid = threadIdx.x;
    const int l = tid & 31, w = tid >> 5;
    const int wm = w >> 1, wn = w & 1;
    const int lq = l >> 2, lr = l & 3;
    const size_t rowbase = (size_t)blockIdx.x * TM;
    const float* X0g = i0 + rowbase * DIM;
    const float* X1g = i1 + rowbase * DIM;
    const uint32_t sb = smem_u32(dyn);

    // job j (0..15): pass p=j>>2, chunk c=j&3
    //   p0: A=X1,B=attn1 (->g0, dot X0)   p1: A=X0,B=attn2 (->g1, dot X1)
    //   p2: A=X0,B=W1 (scale s0)          p3: A=X1,B=W2 (scale s1)
    auto stage = [&](int j) {
        const int p = j >> 2, c = j & 3;
        const float* As = (p == 0 || p == 3) ? X1g : X0g;
        const float* Bs = (p == 0) ? A1 : (p == 1) ? A2 : (p == 2) ? W1 : W2;
        const uint32_t xb = sb + (uint32_t)(j & 1) * (BUF_FLOATS * 4);
        const uint32_t wb = xb + XS_FLOATS * 4;
#pragma unroll
        for (int t = 0; t < 8; ++t) {          // X chunk: 128 x 64
            const int id = tid + t * THREADS;
            const int r = id >> 4, c4 = (id & 15) << 2;
            cp16(xb + (uint32_t)(r * PAD_X + c4) * 4, As + (size_t)r * DIM + c * 64 + c4);
        }
#pragma unroll
        for (int t = 0; t < 16; ++t) {         // W chunk: 64 x 256
            const int id = tid + t * THREADS;
            const int k = id >> 6, n4 = (id & 63) << 2;
            cp16(wb + (uint32_t)(k * PAD_W + n4) * 4, Bs + (size_t)(c * 64 + k) * DIM + n4);
        }
        CP_COMMIT();
    };

    float acc[2][16][4];
    zero_acc(acc);
    float sc[2][2] = {{1.f, 1.f}, {1.f, 1.f}};

    stage(0);
    stage(1);

    for (int j = 0; j < 16; ++j) {
        if (j == 15) { CP_WAIT0(); } else { CP_WAIT1(); }
        __syncthreads();
        const float* xs = dyn + (j & 1) * BUF_FLOATS;
        const float* ws = xs + XS_FLOATS;
        if (j >= 8) gemm_chunk<true>(xs, ws, acc, sc, wm, wn, lq, lr);
        else        gemm_chunk<false>(xs, ws, acc, sc, wm, wn, lq, lr);

        if (j == 3) {                       // g0 = rowdot(U0, X0)
            gate_dot(X0g, acc, 0, wm, wn, lq, lr, s_g);
            zero_acc(acc);
        }
        if (j == 7) {                       // g1 = rowdot(U1, X1); sigmoid; load scales
            gate_dot(X1g, acc, 1, wm, wn, lq, lr, s_g);
            __syncthreads();
            if (tid < 128) {
                const float g0 = s_g[0][0][tid] + s_g[0][1][tid];
                const float g1 = s_g[1][0][tid] + s_g[1][1][tid];
                s_sc[0][tid] = 1.f + 1.f / (1.f + expf(-g0));
                s_sc[1][tid] = 1.f + 1.f / (1.f + expf(-g1));
            }
            __syncthreads();
#pragma unroll
            for (int mt = 0; mt < 2; ++mt) {
                sc[mt][0] = s_sc[0][wm * 32 + mt * 16 + lq];
                sc[mt][1] = s_sc[0][wm * 32 + mt * 16 + lq + 8];
            }
            zero_acc(acc);
        }
        if (j == 11) {                      // switch row scales: s0 -> s1
#pragma unroll
            for (int mt = 0; mt < 2; ++mt) {
                sc[mt][0] = s_sc[1][wm * 32 + mt * 16 + lq];
                sc[mt][1] = s_sc[1][wm * 32 + mt * 16 + lq + 8];
            }
        }
        __syncthreads();                    // all reads of buf (j&1) done
        if (j + 2 < 16) stage(j + 2);
    }

    // epilogue: store out = s0*(X0@W1) + s1*(X1@W2) (already accumulated)
#pragma unroll
    for (int mt = 0; mt < 2; ++mt) {
        const int r0 = wm * 32 + mt * 16 + lq;
#pragma unroll
        for (int nt = 0; nt < 16; ++nt) {
            const int cb = wn * 128 + nt * 8 + lr * 2;
            float2 v0 = make_float2(acc[mt][nt][0], acc[mt][nt][1]);
            float2 v1 = make_float2(acc[mt][nt][2], acc[mt][nt][3]);
            *reinterpret_cast<float2*>(out + (rowbase + r0) * DIM + cb) = v0;
            *reinterpret_cast<float2*>(out + (rowbase + r0 + 8) * DIM + cb) = v1;
        }
    }
}

extern "C" void kernel_launch(void* const* d_in, const int* in_sizes, int n_in,
                              void* d_out, int out_size) {
    const float* i0 = (const float*)d_in[0];
    const float* i1 = (const float*)d_in[1];
    const float* W1 = (const float*)d_in[2];
    const float* W2 = (const float*)d_in[3];
    const float* A1 = (const float*)d_in[4];
    const float* A2 = (const float*)d_in[5];
    float* out = (float*)d_out;

    cudaFuncSetAttribute(fused_mma_kernel,
                         cudaFuncAttributeMaxDynamicSharedMemorySize, SMEM_BYTES);
    const int rows = in_sizes[0] / DIM;          // 65536
    fused_mma_kernel<<<rows / TM, THREADS, SMEM_BYTES>>>(i0, i1, W1, W2, A1, A2, out);
    (void)n_in; (void)out_size;
}